// round 7
// baseline (speedup 1.0000x reference)
#include <cuda_runtime.h>
#include <math.h>
#include <stdint.h>

#define S_LEN 4096
#define D_MODEL 1024
#define N_HEADS 16
#define D_HEAD 64
#define BK 32

// Scratch (allocation-free rule: __device__ globals)
__device__ float g_Qp[S_LEN * D_MODEL];
__device__ float g_Kp[S_LEN * D_MODEL];
__device__ float g_Vp[S_LEN * D_MODEL];
__device__ float g_vals[S_LEN * D_MODEL];
__device__ float g_attn_fallback[(size_t)N_HEADS * S_LEN * S_LEN];

__device__ __forceinline__ float to_tf32(float x) {
    float y;
    asm("cvt.rna.tf32.f32 %0, %1;" : "=f"(y) : "f"(x));
    return y;
}

__device__ __forceinline__ float4 tf32_4(float4 f) {
    return make_float4(to_tf32(f.x), to_tf32(f.y), to_tf32(f.z), to_tf32(f.w));
}

__device__ __forceinline__ void mma_tf32(float& d0, float& d1, float& d2, float& d3,
                                         float a0, float a1, float a2, float a3,
                                         float b0, float b1)
{
    uint32_t ua0 = __float_as_uint(a0), ua1 = __float_as_uint(a1);
    uint32_t ua2 = __float_as_uint(a2), ua3 = __float_as_uint(a3);
    uint32_t ub0 = __float_as_uint(b0), ub1 = __float_as_uint(b1);
    asm volatile(
        "mma.sync.aligned.m16n8k8.row.col.f32.tf32.tf32.f32 "
        "{%0,%1,%2,%3}, {%4,%5,%6,%7}, {%8,%9}, {%0,%1,%2,%3};"
        : "+f"(d0), "+f"(d1), "+f"(d2), "+f"(d3)
        : "r"(ua0), "r"(ua1), "r"(ua2), "r"(ua3), "r"(ub0), "r"(ub1));
}

// ---------------------------------------------------------------------------
// Projection GEMM body: C = A @ B + bias, A [4096,1024], B [1024,1024].
// BM=BN=128, BK=32, 256 threads. Uses blockIdx.x/y for tile coords.
// ---------------------------------------------------------------------------
__device__ __forceinline__ void proj_body(const float* __restrict__ A,
                                          const float* __restrict__ B,
                                          float* __restrict__ C,
                                          const float* __restrict__ bias)
{
    __shared__ __align__(16) float As[128][BK + 4];
    __shared__ __align__(16) float Bs[BK][128 + 4];

    const int m0 = blockIdx.y * 128;
    const int n0 = blockIdx.x * 128;
    const int tid = threadIdx.x;
    const int warp = tid >> 5;
    const int lane = tid & 31;
    const int gid = lane >> 2;
    const int tig = lane & 3;
    const int wm0 = (warp >> 1) * 32;
    const int wn0 = (warp & 1) * 64;

    float acc[2][8][4];
    #pragma unroll
    for (int mi = 0; mi < 2; mi++)
        #pragma unroll
        for (int ni = 0; ni < 8; ni++)
            #pragma unroll
            for (int j = 0; j < 4; j++) acc[mi][ni][j] = 0.f;

    for (int k0 = 0; k0 < D_MODEL; k0 += BK) {
        #pragma unroll
        for (int i = 0; i < 4; i++) {
            int idx = tid + i * 256;
            int r = idx >> 3;
            int kq = (idx & 7) * 4;
            *(float4*)&As[r][kq] =
                tf32_4(*(const float4*)(A + (long)(m0 + r) * D_MODEL + k0 + kq));
        }
        #pragma unroll
        for (int i = 0; i < 4; i++) {
            int idx = tid + i * 256;
            int kr = idx >> 5;
            int nq = (idx & 31) * 4;
            *(float4*)&Bs[kr][nq] =
                tf32_4(*(const float4*)(B + (long)(k0 + kr) * D_MODEL + n0 + nq));
        }
        __syncthreads();

        #pragma unroll
        for (int ks = 0; ks < BK; ks += 8) {
            float af[2][4];
            #pragma unroll
            for (int mi = 0; mi < 2; mi++) {
                af[mi][0] = As[wm0 + mi * 16 + gid][ks + tig];
                af[mi][1] = As[wm0 + mi * 16 + gid + 8][ks + tig];
                af[mi][2] = As[wm0 + mi * 16 + gid][ks + tig + 4];
                af[mi][3] = As[wm0 + mi * 16 + gid + 8][ks + tig + 4];
            }
            float bf[8][2];
            #pragma unroll
            for (int ni = 0; ni < 8; ni++) {
                bf[ni][0] = Bs[ks + tig][wn0 + ni * 8 + gid];
                bf[ni][1] = Bs[ks + tig + 4][wn0 + ni * 8 + gid];
            }
            #pragma unroll
            for (int mi = 0; mi < 2; mi++)
                #pragma unroll
                for (int ni = 0; ni < 8; ni++)
                    mma_tf32(acc[mi][ni][0], acc[mi][ni][1], acc[mi][ni][2], acc[mi][ni][3],
                             af[mi][0], af[mi][1], af[mi][2], af[mi][3],
                             bf[ni][0], bf[ni][1]);
        }
        __syncthreads();
    }

    #pragma unroll
    for (int mi = 0; mi < 2; mi++) {
        int r0 = m0 + wm0 + mi * 16 + gid;
        #pragma unroll
        for (int ni = 0; ni < 8; ni++) {
            int c = n0 + wn0 + ni * 8 + tig * 2;
            float b0 = bias[c], b1 = bias[c + 1];
            *(float2*)&C[(long)r0 * D_MODEL + c] =
                make_float2(acc[mi][ni][0] + b0, acc[mi][ni][1] + b1);
            *(float2*)&C[(long)(r0 + 8) * D_MODEL + c] =
                make_float2(acc[mi][ni][2] + b0, acc[mi][ni][3] + b1);
        }
    }
}

// QKV projections in one launch (z selects which projection)
__global__ void __launch_bounds__(256, 2)
qkv_proj(const float* __restrict__ q, const float* __restrict__ k,
         const float* __restrict__ v,
         const float* __restrict__ Wq, const float* __restrict__ bq,
         const float* __restrict__ Wk, const float* __restrict__ bk,
         const float* __restrict__ Wv, const float* __restrict__ bv,
         float* __restrict__ Qp, float* __restrict__ Kp, float* __restrict__ Vp)
{
    int z = blockIdx.z;
    const float* A = (z == 0) ? q : (z == 1) ? k : v;
    const float* B = (z == 0) ? Wq : (z == 1) ? Wk : Wv;
    const float* bias = (z == 0) ? bq : (z == 1) ? bk : bv;
    float* C = (z == 0) ? Qp : (z == 1) ? Kp : Vp;
    proj_body(A, B, C, bias);
}

__global__ void __launch_bounds__(256, 2)
o_proj(const float* __restrict__ A, const float* __restrict__ B,
       float* __restrict__ C, const float* __restrict__ bias)
{
    proj_body(A, B, C, bias);
}

// ---------------------------------------------------------------------------
// Merged attention: per (mb, h) block of 128 Q rows.
// Phase 0: stage Q, hoist Q mma fragments into registers (used both phases).
// Phase 1: loop 64-wide K tiles (double-buffered, reg-prefetched), accumulate
//          rowsums of exp(scale*QK^T); compute invs[] in smem.
// Phase 2: loop K/V tiles again: S=QK^T, p=exp*inv -> Ps, O += Ps@V,
//          attn written once from Ps (coalesced float4).
// ---------------------------------------------------------------------------
__global__ void __launch_bounds__(256, 1)
attn_kernel(const float* __restrict__ Qp, const float* __restrict__ Kp,
            const float* __restrict__ Vp,
            float* __restrict__ attn, float* __restrict__ vals, float scale)
{
    extern __shared__ __align__(16) float sm[];
    // Layout (floats): Qs[128][68] @0, Ks[2][64][68] @8704, Vs[2][64][68] @17408,
    //                  Ps[128][68] @26112, invs[128] @34816
    float (*Qs)[68] = (float (*)[68])sm;
    float (*Ks)[64][68] = (float (*)[64][68])(sm + 8704);
    float (*Vs)[64][68] = (float (*)[64][68])(sm + 17408);
    float (*Ps)[68] = (float (*)[68])(sm + 26112);
    float* invs = sm + 34816;
    __shared__ float red[2][128];

    const int mb = blockIdx.x, h = blockIdx.y;
    const float* Qg = Qp + (long)mb * 128 * D_MODEL + h * D_HEAD;
    const float* Kg = Kp + h * D_HEAD;
    const float* Vg = Vp + h * D_HEAD;
    const long attn_row0 = (long)h * S_LEN + mb * 128;

    const int tid = threadIdx.x;
    const int warp = tid >> 5;
    const int lane = tid & 31;
    const int gid = lane >> 2;
    const int tig = lane & 3;
    const int wm0 = (warp >> 1) * 32;
    const int wn = warp & 1;
    const int wn0 = wn * 32;

    // ---- Phase 0: stage Q, build register fragments ----
    #pragma unroll
    for (int i = 0; i < 8; i++) {
        int idx = tid + i * 256;
        int r = idx >> 4;
        int c4 = (idx & 15) * 4;
        *(float4*)&Qs[r][c4] = tf32_4(*(const float4*)(Qg + (long)r * D_MODEL + c4));
    }
    __syncthreads();

    float qf[2][8][4];
    #pragma unroll
    for (int mi = 0; mi < 2; mi++) {
        int r = wm0 + mi * 16 + gid;
        #pragma unroll
        for (int ksi = 0; ksi < 8; ksi++) {
            int ks = ksi * 8;
            qf[mi][ksi][0] = Qs[r][ks + tig];
            qf[mi][ksi][1] = Qs[r + 8][ks + tig];
            qf[mi][ksi][2] = Qs[r][ks + tig + 4];
            qf[mi][ksi][3] = Qs[r + 8][ks + tig + 4];
        }
    }

    // ---- Phase 1: rowsums ----
    float rp[2][2] = {{0.f, 0.f}, {0.f, 0.f}};

    // preload K tile 0
    #pragma unroll
    for (int i = 0; i < 4; i++) {
        int idx = tid + i * 256;
        int r = idx >> 4;
        int c4 = (idx & 15) * 4;
        *(float4*)&Ks[0][r][c4] = tf32_4(*(const float4*)(Kg + (long)r * D_MODEL + c4));
    }
    __syncthreads();

    for (int nb = 0; nb < 64; nb++) {
        const int cur = nb & 1, nxt = cur ^ 1;
        const bool pf = (nb + 1) < 64;
        float4 pk[4];
        if (pf) {
            #pragma unroll
            for (int i = 0; i < 4; i++) {
                int idx = tid + i * 256;
                int r = idx >> 4;
                int c4 = (idx & 15) * 4;
                pk[i] = tf32_4(*(const float4*)(Kg + (long)((nb + 1) * 64 + r) * D_MODEL + c4));
            }
        }

        float sacc[2][4][4];
        #pragma unroll
        for (int mi = 0; mi < 2; mi++)
            #pragma unroll
            for (int ni = 0; ni < 4; ni++)
                #pragma unroll
                for (int j = 0; j < 4; j++) sacc[mi][ni][j] = 0.f;

        #pragma unroll
        for (int ksi = 0; ksi < 8; ksi++) {
            int ks = ksi * 8;
            float bf[4][2];
            #pragma unroll
            for (int ni = 0; ni < 4; ni++) {
                bf[ni][0] = Ks[cur][wn0 + ni * 8 + gid][ks + tig];
                bf[ni][1] = Ks[cur][wn0 + ni * 8 + gid][ks + tig + 4];
            }
            #pragma unroll
            for (int mi = 0; mi < 2; mi++)
                #pragma unroll
                for (int ni = 0; ni < 4; ni++)
                    mma_tf32(sacc[mi][ni][0], sacc[mi][ni][1], sacc[mi][ni][2], sacc[mi][ni][3],
                             qf[mi][ksi][0], qf[mi][ksi][1], qf[mi][ksi][2], qf[mi][ksi][3],
                             bf[ni][0], bf[ni][1]);
        }

        #pragma unroll
        for (int mi = 0; mi < 2; mi++)
            #pragma unroll
            for (int ni = 0; ni < 4; ni++) {
                rp[mi][0] += __expf(scale * sacc[mi][ni][0]) + __expf(scale * sacc[mi][ni][1]);
                rp[mi][1] += __expf(scale * sacc[mi][ni][2]) + __expf(scale * sacc[mi][ni][3]);
            }

        if (pf) {
            #pragma unroll
            for (int i = 0; i < 4; i++) {
                int idx = tid + i * 256;
                int r = idx >> 4;
                int c4 = (idx & 15) * 4;
                *(float4*)&Ks[nxt][r][c4] = pk[i];
            }
        }
        __syncthreads();
    }

    // reduce rowsums -> invs
    #pragma unroll
    for (int mi = 0; mi < 2; mi++)
        #pragma unroll
        for (int hh = 0; hh < 2; hh++) {
            rp[mi][hh] += __shfl_xor_sync(0xffffffffu, rp[mi][hh], 1);
            rp[mi][hh] += __shfl_xor_sync(0xffffffffu, rp[mi][hh], 2);
        }
    if (tig == 0) {
        #pragma unroll
        for (int mi = 0; mi < 2; mi++)
            #pragma unroll
            for (int hh = 0; hh < 2; hh++)
                red[wn][wm0 + mi * 16 + gid + 8 * hh] = rp[mi][hh];
    }
    __syncthreads();
    if (tid < 128) invs[tid] = 1.0f / (red[0][tid] + red[1][tid]);
    __syncthreads();

    // ---- Phase 2: attn write + O accumulation ----
    float oacc[2][4][4];
    #pragma unroll
    for (int mi = 0; mi < 2; mi++)
        #pragma unroll
        for (int ni = 0; ni < 4; ni++)
            #pragma unroll
            for (int j = 0; j < 4; j++) oacc[mi][ni][j] = 0.f;

    // preload K/V tile 0
    #pragma unroll
    for (int i = 0; i < 4; i++) {
        int idx = tid + i * 256;
        int r = idx >> 4;
        int c4 = (idx & 15) * 4;
        *(float4*)&Ks[0][r][c4] = tf32_4(*(const float4*)(Kg + (long)r * D_MODEL + c4));
        *(float4*)&Vs[0][r][c4] = tf32_4(*(const float4*)(Vg + (long)r * D_MODEL + c4));
    }
    __syncthreads();

    for (int nb = 0; nb < 64; nb++) {
        const int cur = nb & 1, nxt = cur ^ 1;
        const bool pf = (nb + 1) < 64;
        float4 pk[4], pv[4];
        if (pf) {
            #pragma unroll
            for (int i = 0; i < 4; i++) {
                int idx = tid + i * 256;
                int r = idx >> 4;
                int c4 = (idx & 15) * 4;
                long go = (long)((nb + 1) * 64 + r) * D_MODEL + c4;
                pk[i] = tf32_4(*(const float4*)(Kg + go));
                pv[i] = tf32_4(*(const float4*)(Vg + go));
            }
        }

        // S = Q @ K^T
        float sacc[2][4][4];
        #pragma unroll
        for (int mi = 0; mi < 2; mi++)
            #pragma unroll
            for (int ni = 0; ni < 4; ni++)
                #pragma unroll
                for (int j = 0; j < 4; j++) sacc[mi][ni][j] = 0.f;

        #pragma unroll
        for (int ksi = 0; ksi < 8; ksi++) {
            int ks = ksi * 8;
            float bf[4][2];
            #pragma unroll
            for (int ni = 0; ni < 4; ni++) {
                bf[ni][0] = Ks[cur][wn0 + ni * 8 + gid][ks + tig];
                bf[ni][1] = Ks[cur][wn0 + ni * 8 + gid][ks + tig + 4];
            }
            #pragma unroll
            for (int mi = 0; mi < 2; mi++)
                #pragma unroll
                for (int ni = 0; ni < 4; ni++)
                    mma_tf32(sacc[mi][ni][0], sacc[mi][ni][1], sacc[mi][ni][2], sacc[mi][ni][3],
                             qf[mi][ksi][0], qf[mi][ksi][1], qf[mi][ksi][2], qf[mi][ksi][3],
                             bf[ni][0], bf[ni][1]);
        }

        // p = exp(scale*s) * inv -> Ps
        #pragma unroll
        for (int mi = 0; mi < 2; mi++) {
            int r = wm0 + mi * 16 + gid;
            float iv0 = invs[r], iv1 = invs[r + 8];
            #pragma unroll
            for (int ni = 0; ni < 4; ni++) {
                int c = wn0 + ni * 8 + tig * 2;
                *(float2*)&Ps[r][c] =
                    make_float2(__expf(scale * sacc[mi][ni][0]) * iv0,
                                __expf(scale * sacc[mi][ni][1]) * iv0);
                *(float2*)&Ps[r + 8][c] =
                    make_float2(__expf(scale * sacc[mi][ni][2]) * iv1,
                                __expf(scale * sacc[mi][ni][3]) * iv1);
            }
        }
        __syncthreads();   // Ps complete; all warps past S-mma reads of Ks[cur]

        // O += Ps @ Vs
        #pragma unroll
        for (int ksi = 0; ksi < 8; ksi++) {
            int ks = ksi * 8;
            float af[2][4];
            #pragma unroll
            for (int mi = 0; mi < 2; mi++) {
                af[mi][0] = Ps[wm0 + mi * 16 + gid][ks + tig];
                af[mi][1] = Ps[wm0 + mi * 16 + gid + 8][ks + tig];
                af[mi][2] = Ps[wm0 + mi * 16 + gid][ks + tig + 4];
                af[mi][3] = Ps[wm0 + mi * 16 + gid + 8][ks + tig + 4];
            }
            float bf[4][2];
            #pragma unroll
            for (int ni = 0; ni < 4; ni++) {
                bf[ni][0] = Vs[cur][ks + tig][wn0 + ni * 8 + gid];
                bf[ni][1] = Vs[cur][ks + tig + 4][wn0 + ni * 8 + gid];
            }
            #pragma unroll
            for (int mi = 0; mi < 2; mi++)
                #pragma unroll
                for (int ni = 0; ni < 4; ni++)
                    mma_tf32(oacc[mi][ni][0], oacc[mi][ni][1], oacc[mi][ni][2], oacc[mi][ni][3],
                             af[mi][0], af[mi][1], af[mi][2], af[mi][3],
                             bf[ni][0], bf[ni][1]);
        }

        // write attn tile (128x64) from Ps, coalesced float4
        #pragma unroll
        for (int i = 0; i < 8; i++) {
            int idx = tid + i * 256;
            int r = idx >> 4;
            int c4 = (idx & 15) * 4;
            *(float4*)&attn[(attn_row0 + r) * S_LEN + nb * 64 + c4] =
                *(const float4*)&Ps[r][c4];
        }

        if (pf) {
            #pragma unroll
            for (int i = 0; i < 4; i++) {
                int idx = tid + i * 256;
                int r = idx >> 4;
                int c4 = (idx & 15) * 4;
                *(float4*)&Ks[nxt][r][c4] = pk[i];
                *(float4*)&Vs[nxt][r][c4] = pv[i];
            }
        }
        __syncthreads();   // new tiles visible; Ps safe to overwrite next iter
    }

    // Epilogue: write O
    #pragma unroll
    for (int mi = 0; mi < 2; mi++) {
        int r0 = mb * 128 + wm0 + mi * 16 + gid;
        #pragma unroll
        for (int ni = 0; ni < 4; ni++) {
            int c = h * D_HEAD + wn0 + ni * 8 + tig * 2;
            *(float2*)&vals[(long)r0 * D_MODEL + c] =
                make_float2(oacc[mi][ni][0], oacc[mi][ni][1]);
            *(float2*)&vals[(long)(r0 + 8) * D_MODEL + c] =
                make_float2(oacc[mi][ni][2], oacc[mi][ni][3]);
        }
    }
}

extern "C" void kernel_launch(void* const* d_in, const int* in_sizes, int n_in,
                              void* d_out, int out_size)
{
    const float* q  = (const float*)d_in[0];
    const float* k  = (const float*)d_in[1];
    const float* v  = (const float*)d_in[2];
    const float* Wq = (const float*)d_in[3];
    const float* bq = (const float*)d_in[4];
    const float* Wk = (const float*)d_in[5];
    const float* bk = (const float*)d_in[6];
    const float* Wv = (const float*)d_in[7];
    const float* bv = (const float*)d_in[8];
    const float* Wo = (const float*)d_in[9];
    const float* bo = (const float*)d_in[10];

    float* out = (float*)d_out;

    float *Qp, *Kp, *Vp, *Vals, *attn_fb;
    cudaGetSymbolAddress((void**)&Qp,   g_Qp);
    cudaGetSymbolAddress((void**)&Kp,   g_Kp);
    cudaGetSymbolAddress((void**)&Vp,   g_Vp);
    cudaGetSymbolAddress((void**)&Vals, g_vals);
    cudaGetSymbolAddress((void**)&attn_fb, g_attn_fallback);

    const long OUT_ELEMS  = (long)S_LEN * D_MODEL;
    const long ATTN_ELEMS = (long)N_HEADS * S_LEN * S_LEN;
    float* attn = ((long)out_size >= OUT_ELEMS + ATTN_ELEMS)
                      ? (out + OUT_ELEMS)
                      : attn_fb;

    const int ATTN_SMEM = (34816 + 128) * (int)sizeof(float);   // ~139.8 KB
    static bool attr_done = false;
    if (!attr_done) {
        cudaFuncSetAttribute(attn_kernel,
                             cudaFuncAttributeMaxDynamicSharedMemorySize, ATTN_SMEM);
        attr_done = true;
    }

    dim3 blk(256);
    const float scale = 1.0f / sqrtf((float)D_HEAD);

    // 1) QKV projections in one launch
    dim3 gQKV(D_MODEL / 128, S_LEN / 128, 3);
    qkv_proj<<<gQKV, blk>>>(q, k, v, Wq, bq, Wk, bk, Wv, bv, Qp, Kp, Vp);

    // 2) Merged attention (rowsum + attn write + O)
    dim3 gA(S_LEN / 128, N_HEADS);
    attn_kernel<<<gA, blk, ATTN_SMEM>>>(Qp, Kp, Vp, attn, Vals, scale);

    // 3) out = vals @ Wo + bo
    dim3 gProj(D_MODEL / 128, S_LEN / 128, 1);
    o_proj<<<gProj, blk>>>(Vals, Wo, out, D_MODEL == 1024 ? bo : bo);
}

// round 8
// speedup vs baseline: 1.1863x; 1.1863x over previous
#include <cuda_runtime.h>
#include <math.h>
#include <stdint.h>

#define S_LEN 4096
#define D_MODEL 1024
#define N_HEADS 16
#define D_HEAD 64
#define BK 32

// Scratch (allocation-free rule: __device__ globals)
__device__ float g_Qp[S_LEN * D_MODEL];
__device__ float g_Kp[S_LEN * D_MODEL];
__device__ float g_Vp[S_LEN * D_MODEL];
__device__ float g_vals[S_LEN * D_MODEL];
__device__ float g_inv[(size_t)N_HEADS * S_LEN];  // 1 / rowsum
__device__ float g_attn_fallback[(size_t)N_HEADS * S_LEN * S_LEN];

__device__ __forceinline__ float to_tf32(float x) {
    float y;
    asm("cvt.rna.tf32.f32 %0, %1;" : "=f"(y) : "f"(x));
    return y;
}

__device__ __forceinline__ float4 tf32_4(float4 f) {
    return make_float4(to_tf32(f.x), to_tf32(f.y), to_tf32(f.z), to_tf32(f.w));
}

__device__ __forceinline__ void mma_tf32(float& d0, float& d1, float& d2, float& d3,
                                         float a0, float a1, float a2, float a3,
                                         float b0, float b1)
{
    uint32_t ua0 = __float_as_uint(a0), ua1 = __float_as_uint(a1);
    uint32_t ua2 = __float_as_uint(a2), ua3 = __float_as_uint(a3);
    uint32_t ub0 = __float_as_uint(b0), ub1 = __float_as_uint(b1);
    asm volatile(
        "mma.sync.aligned.m16n8k8.row.col.f32.tf32.tf32.f32 "
        "{%0,%1,%2,%3}, {%4,%5,%6,%7}, {%8,%9}, {%0,%1,%2,%3};"
        : "+f"(d0), "+f"(d1), "+f"(d2), "+f"(d3)
        : "r"(ua0), "r"(ua1), "r"(ua2), "r"(ua3), "r"(ub0), "r"(ub1));
}

// ---------------------------------------------------------------------------
// Projection GEMM body: C = A @ B + bias. BM=BN=128, BK=32, 256 threads.
// ---------------------------------------------------------------------------
__device__ __forceinline__ void proj_body(const float* __restrict__ A,
                                          const float* __restrict__ B,
                                          float* __restrict__ C,
                                          const float* __restrict__ bias)
{
    __shared__ __align__(16) float As[128][BK + 4];
    __shared__ __align__(16) float Bs[BK][128 + 4];

    const int m0 = blockIdx.y * 128;
    const int n0 = blockIdx.x * 128;
    const int tid = threadIdx.x;
    const int warp = tid >> 5;
    const int lane = tid & 31;
    const int gid = lane >> 2;
    const int tig = lane & 3;
    const int wm0 = (warp >> 1) * 32;
    const int wn0 = (warp & 1) * 64;

    float acc[2][8][4];
    #pragma unroll
    for (int mi = 0; mi < 2; mi++)
        #pragma unroll
        for (int ni = 0; ni < 8; ni++)
            #pragma unroll
            for (int j = 0; j < 4; j++) acc[mi][ni][j] = 0.f;

    for (int k0 = 0; k0 < D_MODEL; k0 += BK) {
        #pragma unroll
        for (int i = 0; i < 4; i++) {
            int idx = tid + i * 256;
            int r = idx >> 3;
            int kq = (idx & 7) * 4;
            *(float4*)&As[r][kq] =
                tf32_4(*(const float4*)(A + (long)(m0 + r) * D_MODEL + k0 + kq));
        }
        #pragma unroll
        for (int i = 0; i < 4; i++) {
            int idx = tid + i * 256;
            int kr = idx >> 5;
            int nq = (idx & 31) * 4;
            *(float4*)&Bs[kr][nq] =
                tf32_4(*(const float4*)(B + (long)(k0 + kr) * D_MODEL + n0 + nq));
        }
        __syncthreads();

        #pragma unroll
        for (int ks = 0; ks < BK; ks += 8) {
            float af[2][4];
            #pragma unroll
            for (int mi = 0; mi < 2; mi++) {
                af[mi][0] = As[wm0 + mi * 16 + gid][ks + tig];
                af[mi][1] = As[wm0 + mi * 16 + gid + 8][ks + tig];
                af[mi][2] = As[wm0 + mi * 16 + gid][ks + tig + 4];
                af[mi][3] = As[wm0 + mi * 16 + gid + 8][ks + tig + 4];
            }
            float bf[8][2];
            #pragma unroll
            for (int ni = 0; ni < 8; ni++) {
                bf[ni][0] = Bs[ks + tig][wn0 + ni * 8 + gid];
                bf[ni][1] = Bs[ks + tig + 4][wn0 + ni * 8 + gid];
            }
            #pragma unroll
            for (int mi = 0; mi < 2; mi++)
                #pragma unroll
                for (int ni = 0; ni < 8; ni++)
                    mma_tf32(acc[mi][ni][0], acc[mi][ni][1], acc[mi][ni][2], acc[mi][ni][3],
                             af[mi][0], af[mi][1], af[mi][2], af[mi][3],
                             bf[ni][0], bf[ni][1]);
        }
        __syncthreads();
    }

    #pragma unroll
    for (int mi = 0; mi < 2; mi++) {
        int r0 = m0 + wm0 + mi * 16 + gid;
        #pragma unroll
        for (int ni = 0; ni < 8; ni++) {
            int c = n0 + wn0 + ni * 8 + tig * 2;
            float b0 = bias[c], b1 = bias[c + 1];
            *(float2*)&C[(long)r0 * D_MODEL + c] =
                make_float2(acc[mi][ni][0] + b0, acc[mi][ni][1] + b1);
            *(float2*)&C[(long)(r0 + 8) * D_MODEL + c] =
                make_float2(acc[mi][ni][2] + b0, acc[mi][ni][3] + b1);
        }
    }
}

// QKV projections in one launch (z selects which projection)
__global__ void __launch_bounds__(256, 2)
qkv_proj(const float* __restrict__ q, const float* __restrict__ k,
         const float* __restrict__ v,
         const float* __restrict__ Wq, const float* __restrict__ bq,
         const float* __restrict__ Wk, const float* __restrict__ bk,
         const float* __restrict__ Wv, const float* __restrict__ bv,
         float* __restrict__ Qp, float* __restrict__ Kp, float* __restrict__ Vp)
{
    int z = blockIdx.z;
    const float* A = (z == 0) ? q : (z == 1) ? k : v;
    const float* B = (z == 0) ? Wq : (z == 1) ? Wk : Wv;
    const float* bias = (z == 0) ? bq : (z == 1) ? bk : bv;
    float* C = (z == 0) ? Qp : (z == 1) ? Kp : Vp;
    proj_body(A, B, C, bias);
}

__global__ void __launch_bounds__(256, 2)
o_proj(const float* __restrict__ A, const float* __restrict__ B,
       float* __restrict__ C, const float* __restrict__ bias)
{
    proj_body(A, B, C, bias);
}

// ---------------------------------------------------------------------------
// Rowsum pass: for each (mb, h), recompute s = scale*Q@K^T over all columns,
// accumulate sum of exp(s) per row in registers, write inv = 1/sum.
// ---------------------------------------------------------------------------
__global__ void __launch_bounds__(256, 2)
rowsum_kernel(const float* __restrict__ Qp, const float* __restrict__ Kp,
              float* __restrict__ inv, float scale)
{
    extern __shared__ __align__(16) float sm[];
    float (*Qs)[D_HEAD + 4] = (float (*)[D_HEAD + 4])sm;
    float (*Ks)[D_HEAD + 4] = (float (*)[D_HEAD + 4])(sm + 128 * (D_HEAD + 4));
    __shared__ float red[2][128];

    const int mb = blockIdx.x, h = blockIdx.y;
    const float* Aq = Qp + (long)mb * 128 * D_MODEL + h * D_HEAD;

    const int tid = threadIdx.x;
    const int warp = tid >> 5;
    const int lane = tid & 31;
    const int gid = lane >> 2;
    const int tig = lane & 3;
    const int wm0 = (warp >> 1) * 32;
    const int wn = warp & 1;
    const int wn0 = wn * 64;

    #pragma unroll
    for (int i = 0; i < 8; i++) {
        int idx = tid + i * 256;
        int r = idx >> 4;
        int c4 = (idx & 15) * 4;
        *(float4*)&Qs[r][c4] = tf32_4(*(const float4*)(Aq + (long)r * D_MODEL + c4));
    }

    float rp[2][2] = {{0.f, 0.f}, {0.f, 0.f}};

    for (int nb = 0; nb < S_LEN / 128; nb++) {
        const float* Bk = Kp + (long)nb * 128 * D_MODEL + h * D_HEAD;
        __syncthreads();
        #pragma unroll
        for (int i = 0; i < 8; i++) {
            int idx = tid + i * 256;
            int r = idx >> 4;
            int c4 = (idx & 15) * 4;
            *(float4*)&Ks[r][c4] = tf32_4(*(const float4*)(Bk + (long)r * D_MODEL + c4));
        }
        __syncthreads();

        float acc[2][8][4];
        #pragma unroll
        for (int mi = 0; mi < 2; mi++)
            #pragma unroll
            for (int ni = 0; ni < 8; ni++)
                #pragma unroll
                for (int j = 0; j < 4; j++) acc[mi][ni][j] = 0.f;

        #pragma unroll
        for (int ks = 0; ks < D_HEAD; ks += 8) {
            float af[2][4];
            #pragma unroll
            for (int mi = 0; mi < 2; mi++) {
                af[mi][0] = Qs[wm0 + mi * 16 + gid][ks + tig];
                af[mi][1] = Qs[wm0 + mi * 16 + gid + 8][ks + tig];
                af[mi][2] = Qs[wm0 + mi * 16 + gid][ks + tig + 4];
                af[mi][3] = Qs[wm0 + mi * 16 + gid + 8][ks + tig + 4];
            }
            float bf[8][2];
            #pragma unroll
            for (int ni = 0; ni < 8; ni++) {
                bf[ni][0] = Ks[wn0 + ni * 8 + gid][ks + tig];
                bf[ni][1] = Ks[wn0 + ni * 8 + gid][ks + tig + 4];
            }
            #pragma unroll
            for (int mi = 0; mi < 2; mi++)
                #pragma unroll
                for (int ni = 0; ni < 8; ni++)
                    mma_tf32(acc[mi][ni][0], acc[mi][ni][1], acc[mi][ni][2], acc[mi][ni][3],
                             af[mi][0], af[mi][1], af[mi][2], af[mi][3],
                             bf[ni][0], bf[ni][1]);
        }

        #pragma unroll
        for (int mi = 0; mi < 2; mi++)
            #pragma unroll
            for (int ni = 0; ni < 8; ni++) {
                rp[mi][0] += __expf(scale * acc[mi][ni][0]) + __expf(scale * acc[mi][ni][1]);
                rp[mi][1] += __expf(scale * acc[mi][ni][2]) + __expf(scale * acc[mi][ni][3]);
            }
    }

    #pragma unroll
    for (int mi = 0; mi < 2; mi++)
        #pragma unroll
        for (int hh = 0; hh < 2; hh++) {
            rp[mi][hh] += __shfl_xor_sync(0xffffffffu, rp[mi][hh], 1);
            rp[mi][hh] += __shfl_xor_sync(0xffffffffu, rp[mi][hh], 2);
        }
    if (tig == 0) {
        #pragma unroll
        for (int mi = 0; mi < 2; mi++)
            #pragma unroll
            for (int hh = 0; hh < 2; hh++)
                red[wn][wm0 + mi * 16 + gid + 8 * hh] = rp[mi][hh];
    }
    __syncthreads();
    if (tid < 128) {
        long row = (long)h * S_LEN + mb * 128 + tid;
        inv[row] = 1.0f / (red[0][tid] + red[1][tid]);
    }
}

// ---------------------------------------------------------------------------
// Fused attention: for each (mb, h), loop over 64-wide K/V tiles:
//   S = Q@K^T (mma), p = exp(scale*s)*inv[row] -> staged in smem Ps,
//   O += Ps@V (mma), attn written once via coalesced float4 from Ps.
// ---------------------------------------------------------------------------
__global__ void __launch_bounds__(256, 2)
fused_attn_kernel(const float* __restrict__ Qp, const float* __restrict__ Kp,
                  const float* __restrict__ Vp, const float* __restrict__ invp,
                  float* __restrict__ attn, float* __restrict__ vals, float scale)
{
    extern __shared__ __align__(16) float sm[];
    const int LD = D_HEAD + 4;
    float (*Qs)[D_HEAD + 4] = (float (*)[D_HEAD + 4])sm;
    float (*Ks)[D_HEAD + 4] = (float (*)[D_HEAD + 4])(sm + 128 * LD);
    float (*Vs)[D_HEAD + 4] = (float (*)[D_HEAD + 4])(sm + 192 * LD);
    float (*Ps)[D_HEAD + 4] = (float (*)[D_HEAD + 4])(sm + 256 * LD);
    float* invs = sm + 384 * LD;

    const int mb = blockIdx.x, h = blockIdx.y;
    const float* Aq = Qp + (long)mb * 128 * D_MODEL + h * D_HEAD;
    const long attn_row0 = (long)h * S_LEN + mb * 128;

    const int tid = threadIdx.x;
    const int warp = tid >> 5;
    const int lane = tid & 31;
    const int gid = lane >> 2;
    const int tig = lane & 3;
    const int wm0 = (warp >> 1) * 32;
    const int wn0 = (warp & 1) * 32;

    // Stage Q (tf32) and inv
    #pragma unroll
    for (int i = 0; i < 8; i++) {
        int idx = tid + i * 256;
        int r = idx >> 4;
        int c4 = (idx & 15) * 4;
        *(float4*)&Qs[r][c4] = tf32_4(*(const float4*)(Aq + (long)r * D_MODEL + c4));
    }
    if (tid < 128) invs[tid] = invp[attn_row0 + tid];

    float oacc[2][4][4];
    #pragma unroll
    for (int mi = 0; mi < 2; mi++)
        #pragma unroll
        for (int ni = 0; ni < 4; ni++)
            #pragma unroll
            for (int j = 0; j < 4; j++) oacc[mi][ni][j] = 0.f;

    for (int nb = 0; nb < S_LEN / D_HEAD; nb++) {
        __syncthreads();   // protect Ks/Vs/Ps from previous iteration users
        // Load K, V 64x64 tiles
        #pragma unroll
        for (int i = 0; i < 4; i++) {
            int idx = tid + i * 256;
            int r = idx >> 4;
            int c4 = (idx & 15) * 4;
            const float* gk = Kp + (long)(nb * 64 + r) * D_MODEL + h * D_HEAD + c4;
            *(float4*)&Ks[r][c4] = tf32_4(*(const float4*)gk);
            const float* gv = Vp + (long)(nb * 64 + r) * D_MODEL + h * D_HEAD + c4;
            *(float4*)&Vs[r][c4] = tf32_4(*(const float4*)gv);
        }
        __syncthreads();

        // S = Q @ K^T  (128 x 64)
        float acc[2][4][4];
        #pragma unroll
        for (int mi = 0; mi < 2; mi++)
            #pragma unroll
            for (int ni = 0; ni < 4; ni++)
                #pragma unroll
                for (int j = 0; j < 4; j++) acc[mi][ni][j] = 0.f;

        #pragma unroll
        for (int ks = 0; ks < D_HEAD; ks += 8) {
            float af[2][4];
            #pragma unroll
            for (int mi = 0; mi < 2; mi++) {
                af[mi][0] = Qs[wm0 + mi * 16 + gid][ks + tig];
                af[mi][1] = Qs[wm0 + mi * 16 + gid + 8][ks + tig];
                af[mi][2] = Qs[wm0 + mi * 16 + gid][ks + tig + 4];
                af[mi][3] = Qs[wm0 + mi * 16 + gid + 8][ks + tig + 4];
            }
            float bf[4][2];
            #pragma unroll
            for (int ni = 0; ni < 4; ni++) {
                bf[ni][0] = Ks[wn0 + ni * 8 + gid][ks + tig];
                bf[ni][1] = Ks[wn0 + ni * 8 + gid][ks + tig + 4];
            }
            #pragma unroll
            for (int mi = 0; mi < 2; mi++)
                #pragma unroll
                for (int ni = 0; ni < 4; ni++)
                    mma_tf32(acc[mi][ni][0], acc[mi][ni][1], acc[mi][ni][2], acc[mi][ni][3],
                             af[mi][0], af[mi][1], af[mi][2], af[mi][3],
                             bf[ni][0], bf[ni][1]);
        }

        // p = exp(scale*s) * inv -> Ps
        #pragma unroll
        for (int mi = 0; mi < 2; mi++) {
            int r = wm0 + mi * 16 + gid;
            float iv0 = invs[r], iv1 = invs[r + 8];
            #pragma unroll
            for (int ni = 0; ni < 4; ni++) {
                int c = wn0 + ni * 8 + tig * 2;
                *(float2*)&Ps[r][c] =
                    make_float2(__expf(scale * acc[mi][ni][0]) * iv0,
                                __expf(scale * acc[mi][ni][1]) * iv0);
                *(float2*)&Ps[r + 8][c] =
                    make_float2(__expf(scale * acc[mi][ni][2]) * iv1,
                                __expf(scale * acc[mi][ni][3]) * iv1);
            }
        }
        __syncthreads();

        // O += Ps @ Vs  (128 x 64, K=64)
        #pragma unroll
        for (int ks = 0; ks < D_HEAD; ks += 8) {
            float af[2][4];
            #pragma unroll
            for (int mi = 0; mi < 2; mi++) {
                af[mi][0] = Ps[wm0 + mi * 16 + gid][ks + tig];
                af[mi][1] = Ps[wm0 + mi * 16 + gid + 8][ks + tig];
                af[mi][2] = Ps[wm0 + mi * 16 + gid][ks + tig + 4];
                af[mi][3] = Ps[wm0 + mi * 16 + gid + 8][ks + tig + 4];
            }
            float bf[4][2];
            #pragma unroll
            for (int ni = 0; ni < 4; ni++) {
                bf[ni][0] = Vs[ks + tig][wn0 + ni * 8 + gid];
                bf[ni][1] = Vs[ks + tig + 4][wn0 + ni * 8 + gid];
            }
            #pragma unroll
            for (int mi = 0; mi < 2; mi++)
                #pragma unroll
                for (int ni = 0; ni < 4; ni++)
                    mma_tf32(oacc[mi][ni][0], oacc[mi][ni][1], oacc[mi][ni][2], oacc[mi][ni][3],
                             af[mi][0], af[mi][1], af[mi][2], af[mi][3],
                             bf[ni][0], bf[ni][1]);
        }

        // Write attn tile from Ps, fully coalesced float4 (128x64 = 2048 float4s)
        #pragma unroll
        for (int i = 0; i < 8; i++) {
            int idx = tid + i * 256;
            int r = idx >> 4;
            int c4 = (idx & 15) * 4;
            *(float4*)&attn[(attn_row0 + r) * S_LEN + nb * 64 + c4] =
                *(const float4*)&Ps[r][c4];
        }
    }

    // Epilogue: write O
    #pragma unroll
    for (int mi = 0; mi < 2; mi++) {
        int r0 = mb * 128 + wm0 + mi * 16 + gid;
        #pragma unroll
        for (int ni = 0; ni < 4; ni++) {
            int c = h * D_HEAD + wn0 + ni * 8 + tig * 2;
            *(float2*)&vals[(long)r0 * D_MODEL + c] =
                make_float2(oacc[mi][ni][0], oacc[mi][ni][1]);
            *(float2*)&vals[(long)(r0 + 8) * D_MODEL + c] =
                make_float2(oacc[mi][ni][2], oacc[mi][ni][3]);
        }
    }
}

extern "C" void kernel_launch(void* const* d_in, const int* in_sizes, int n_in,
                              void* d_out, int out_size)
{
    const float* q  = (const float*)d_in[0];
    const float* k  = (const float*)d_in[1];
    const float* v  = (const float*)d_in[2];
    const float* Wq = (const float*)d_in[3];
    const float* bq = (const float*)d_in[4];
    const float* Wk = (const float*)d_in[5];
    const float* bk = (const float*)d_in[6];
    const float* Wv = (const float*)d_in[7];
    const float* bv = (const float*)d_in[8];
    const float* Wo = (const float*)d_in[9];
    const float* bo = (const float*)d_in[10];

    float* out = (float*)d_out;

    float *Qp, *Kp, *Vp, *Vals, *Inv, *attn_fb;
    cudaGetSymbolAddress((void**)&Qp,   g_Qp);
    cudaGetSymbolAddress((void**)&Kp,   g_Kp);
    cudaGetSymbolAddress((void**)&Vp,   g_Vp);
    cudaGetSymbolAddress((void**)&Vals, g_vals);
    cudaGetSymbolAddress((void**)&Inv,  g_inv);
    cudaGetSymbolAddress((void**)&attn_fb, g_attn_fallback);

    const long OUT_ELEMS  = (long)S_LEN * D_MODEL;
    const long ATTN_ELEMS = (long)N_HEADS * S_LEN * S_LEN;
    float* attn = ((long)out_size >= OUT_ELEMS + ATTN_ELEMS)
                      ? (out + OUT_ELEMS)
                      : attn_fb;

    const int LD = D_HEAD + 4;
    const int ROWSUM_SMEM = 2 * 128 * LD * (int)sizeof(float);           // ~69.6 KB
    const int FUSED_SMEM  = (384 * LD + 128) * (int)sizeof(float);       // ~105 KB
    static bool attr_done = false;
    if (!attr_done) {
        cudaFuncSetAttribute(rowsum_kernel,
                             cudaFuncAttributeMaxDynamicSharedMemorySize, ROWSUM_SMEM);
        cudaFuncSetAttribute(fused_attn_kernel,
                             cudaFuncAttributeMaxDynamicSharedMemorySize, FUSED_SMEM);
        attr_done = true;
    }

    dim3 blk(256);
    const float scale = 1.0f / sqrtf((float)D_HEAD);

    // 1) QKV projections in one launch
    dim3 gQKV(D_MODEL / 128, S_LEN / 128, 3);
    qkv_proj<<<gQKV, blk>>>(q, k, v, Wq, bq, Wk, bk, Wv, bv, Qp, Kp, Vp);

    // 2) Row sums -> inv
    dim3 gRS(S_LEN / 128, N_HEADS);
    rowsum_kernel<<<gRS, blk, ROWSUM_SMEM>>>(Qp, Kp, Inv, scale);

    // 3) Fused: recompute scores, normalize, write attn once, O = P@V
    dim3 gF(S_LEN / 128, N_HEADS);
    fused_attn_kernel<<<gF, blk, FUSED_SMEM>>>(Qp, Kp, Vp, Inv, attn, Vals, scale);

    // 4) out = vals @ Wo + bo
    dim3 gProj(D_MODEL / 128, S_LEN / 128, 1);
    o_proj<<<gProj, blk>>>(Vals, Wo, out, bo);
}

// round 9
// speedup vs baseline: 1.2314x; 1.0380x over previous
#include <cuda_runtime.h>
#include <math.h>
#include <stdint.h>

#define S_LEN 4096
#define D_MODEL 1024
#define N_HEADS 16
#define D_HEAD 64
#define BK 32

// Scratch (allocation-free rule: __device__ globals)
__device__ float g_Qp[S_LEN * D_MODEL];
__device__ float g_Kp[S_LEN * D_MODEL];
__device__ float g_Vp[S_LEN * D_MODEL];
__device__ float g_vals[S_LEN * D_MODEL];
__device__ float g_inv[(size_t)N_HEADS * S_LEN];  // 1 / rowsum
__device__ float g_attn_fallback[(size_t)N_HEADS * S_LEN * S_LEN];

__device__ __forceinline__ float to_tf32(float x) {
    float y;
    asm("cvt.rna.tf32.f32 %0, %1;" : "=f"(y) : "f"(x));
    return y;
}

__device__ __forceinline__ float4 tf32_4(float4 f) {
    return make_float4(to_tf32(f.x), to_tf32(f.y), to_tf32(f.z), to_tf32(f.w));
}

__device__ __forceinline__ uint32_t smem_u32(const void* p) {
    return (uint32_t)__cvta_generic_to_shared(p);
}

// ldmatrix x4: four 8x8 b16 tiles == four 8-row x 4-tf32-col blocks.
__device__ __forceinline__ void ldsm_x4(uint32_t& r0, uint32_t& r1,
                                        uint32_t& r2, uint32_t& r3, uint32_t addr)
{
    asm volatile("ldmatrix.sync.aligned.m8n8.x4.shared.b16 {%0,%1,%2,%3}, [%4];"
                 : "=r"(r0), "=r"(r1), "=r"(r2), "=r"(r3) : "r"(addr));
}

__device__ __forceinline__ void mma_tf32(float& d0, float& d1, float& d2, float& d3,
                                         float a0, float a1, float a2, float a3,
                                         float b0, float b1)
{
    uint32_t ua0 = __float_as_uint(a0), ua1 = __float_as_uint(a1);
    uint32_t ua2 = __float_as_uint(a2), ua3 = __float_as_uint(a3);
    uint32_t ub0 = __float_as_uint(b0), ub1 = __float_as_uint(b1);
    asm volatile(
        "mma.sync.aligned.m16n8k8.row.col.f32.tf32.tf32.f32 "
        "{%0,%1,%2,%3}, {%4,%5,%6,%7}, {%8,%9}, {%0,%1,%2,%3};"
        : "+f"(d0), "+f"(d1), "+f"(d2), "+f"(d3)
        : "r"(ua0), "r"(ua1), "r"(ua2), "r"(ua3), "r"(ub0), "r"(ub1));
}

__device__ __forceinline__ void mma_tf32u(float& d0, float& d1, float& d2, float& d3,
                                          uint32_t a0, uint32_t a1, uint32_t a2, uint32_t a3,
                                          uint32_t b0, uint32_t b1)
{
    asm volatile(
        "mma.sync.aligned.m16n8k8.row.col.f32.tf32.tf32.f32 "
        "{%0,%1,%2,%3}, {%4,%5,%6,%7}, {%8,%9}, {%0,%1,%2,%3};"
        : "+f"(d0), "+f"(d1), "+f"(d2), "+f"(d3)
        : "r"(a0), "r"(a1), "r"(a2), "r"(a3), "r"(b0), "r"(b1));
}

// ---------------------------------------------------------------------------
// Projection GEMM body: C = A @ B + bias. BM=BN=128, BK=32, 256 threads.
// (unchanged from round 8)
// ---------------------------------------------------------------------------
__device__ __forceinline__ void proj_body(const float* __restrict__ A,
                                          const float* __restrict__ B,
                                          float* __restrict__ C,
                                          const float* __restrict__ bias)
{
    __shared__ __align__(16) float As[128][BK + 4];
    __shared__ __align__(16) float Bs[BK][128 + 4];

    const int m0 = blockIdx.y * 128;
    const int n0 = blockIdx.x * 128;
    const int tid = threadIdx.x;
    const int warp = tid >> 5;
    const int lane = tid & 31;
    const int gid = lane >> 2;
    const int tig = lane & 3;
    const int wm0 = (warp >> 1) * 32;
    const int wn0 = (warp & 1) * 64;

    float acc[2][8][4];
    #pragma unroll
    for (int mi = 0; mi < 2; mi++)
        #pragma unroll
        for (int ni = 0; ni < 8; ni++)
            #pragma unroll
            for (int j = 0; j < 4; j++) acc[mi][ni][j] = 0.f;

    for (int k0 = 0; k0 < D_MODEL; k0 += BK) {
        #pragma unroll
        for (int i = 0; i < 4; i++) {
            int idx = tid + i * 256;
            int r = idx >> 3;
            int kq = (idx & 7) * 4;
            *(float4*)&As[r][kq] =
                tf32_4(*(const float4*)(A + (long)(m0 + r) * D_MODEL + k0 + kq));
        }
        #pragma unroll
        for (int i = 0; i < 4; i++) {
            int idx = tid + i * 256;
            int kr = idx >> 5;
            int nq = (idx & 31) * 4;
            *(float4*)&Bs[kr][nq] =
                tf32_4(*(const float4*)(B + (long)(k0 + kr) * D_MODEL + n0 + nq));
        }
        __syncthreads();

        #pragma unroll
        for (int ks = 0; ks < BK; ks += 8) {
            float af[2][4];
            #pragma unroll
            for (int mi = 0; mi < 2; mi++) {
                af[mi][0] = As[wm0 + mi * 16 + gid][ks + tig];
                af[mi][1] = As[wm0 + mi * 16 + gid + 8][ks + tig];
                af[mi][2] = As[wm0 + mi * 16 + gid][ks + tig + 4];
                af[mi][3] = As[wm0 + mi * 16 + gid + 8][ks + tig + 4];
            }
            float bf[8][2];
            #pragma unroll
            for (int ni = 0; ni < 8; ni++) {
                bf[ni][0] = Bs[ks + tig][wn0 + ni * 8 + gid];
                bf[ni][1] = Bs[ks + tig + 4][wn0 + ni * 8 + gid];
            }
            #pragma unroll
            for (int mi = 0; mi < 2; mi++)
                #pragma unroll
                for (int ni = 0; ni < 8; ni++)
                    mma_tf32(acc[mi][ni][0], acc[mi][ni][1], acc[mi][ni][2], acc[mi][ni][3],
                             af[mi][0], af[mi][1], af[mi][2], af[mi][3],
                             bf[ni][0], bf[ni][1]);
        }
        __syncthreads();
    }

    #pragma unroll
    for (int mi = 0; mi < 2; mi++) {
        int r0 = m0 + wm0 + mi * 16 + gid;
        #pragma unroll
        for (int ni = 0; ni < 8; ni++) {
            int c = n0 + wn0 + ni * 8 + tig * 2;
            float b0 = bias[c], b1 = bias[c + 1];
            *(float2*)&C[(long)r0 * D_MODEL + c] =
                make_float2(acc[mi][ni][0] + b0, acc[mi][ni][1] + b1);
            *(float2*)&C[(long)(r0 + 8) * D_MODEL + c] =
                make_float2(acc[mi][ni][2] + b0, acc[mi][ni][3] + b1);
        }
    }
}

// QKV projections in one launch (z selects which projection)
__global__ void __launch_bounds__(256, 2)
qkv_proj(const float* __restrict__ q, const float* __restrict__ k,
         const float* __restrict__ v,
         const float* __restrict__ Wq, const float* __restrict__ bq,
         const float* __restrict__ Wk, const float* __restrict__ bk,
         const float* __restrict__ Wv, const float* __restrict__ bv,
         float* __restrict__ Qp, float* __restrict__ Kp, float* __restrict__ Vp)
{
    int z = blockIdx.z;
    const float* A = (z == 0) ? q : (z == 1) ? k : v;
    const float* B = (z == 0) ? Wq : (z == 1) ? Wk : Wv;
    const float* bias = (z == 0) ? bq : (z == 1) ? bk : bv;
    float* C = (z == 0) ? Qp : (z == 1) ? Kp : Vp;
    proj_body(A, B, C, bias);
}

__global__ void __launch_bounds__(256, 2)
o_proj(const float* __restrict__ A, const float* __restrict__ B,
       float* __restrict__ C, const float* __restrict__ bias)
{
    proj_body(A, B, C, bias);
}

// ---------------------------------------------------------------------------
// Rowsum pass with LDSM fragment loads.
// ---------------------------------------------------------------------------
__global__ void __launch_bounds__(256, 2)
rowsum_kernel(const float* __restrict__ Qp, const float* __restrict__ Kp,
              float* __restrict__ inv, float scale)
{
    extern __shared__ __align__(16) float sm[];
    float (*Qs)[D_HEAD + 4] = (float (*)[D_HEAD + 4])sm;
    float (*Ks)[D_HEAD + 4] = (float (*)[D_HEAD + 4])(sm + 128 * (D_HEAD + 4));
    __shared__ float red[2][128];

    const int mb = blockIdx.x, h = blockIdx.y;
    const float* Aq = Qp + (long)mb * 128 * D_MODEL + h * D_HEAD;

    const int tid = threadIdx.x;
    const int warp = tid >> 5;
    const int lane = tid & 31;
    const int gid = lane >> 2;
    const int tig = lane & 3;
    const int wm0 = (warp >> 1) * 32;
    const int wn = warp & 1;
    const int wn0 = wn * 64;

    // LDSM lane-address components
    const int arow = lane & 15;                       // A-side row within 16
    const int acol = (lane >> 4) << 2;                // 0 or 4
    const int brow = (lane & 7) + ((lane >> 4) << 3); // B-side row within 16
    const int bcol = ((lane >> 3) & 1) << 2;          // 0 or 4

    #pragma unroll
    for (int i = 0; i < 8; i++) {
        int idx = tid + i * 256;
        int r = idx >> 4;
        int c4 = (idx & 15) * 4;
        *(float4*)&Qs[r][c4] = tf32_4(*(const float4*)(Aq + (long)r * D_MODEL + c4));
    }

    uint32_t qa[2];
    #pragma unroll
    for (int mi = 0; mi < 2; mi++)
        qa[mi] = smem_u32(&Qs[wm0 + mi * 16 + arow][acol]);
    uint32_t kb[4];
    #pragma unroll
    for (int p = 0; p < 4; p++)
        kb[p] = smem_u32(&Ks[wn0 + p * 16 + brow][bcol]);

    float rp[2][2] = {{0.f, 0.f}, {0.f, 0.f}};

    for (int nb = 0; nb < S_LEN / 128; nb++) {
        const float* Bk = Kp + (long)nb * 128 * D_MODEL + h * D_HEAD;
        __syncthreads();
        #pragma unroll
        for (int i = 0; i < 8; i++) {
            int idx = tid + i * 256;
            int r = idx >> 4;
            int c4 = (idx & 15) * 4;
            *(float4*)&Ks[r][c4] = tf32_4(*(const float4*)(Bk + (long)r * D_MODEL + c4));
        }
        __syncthreads();

        float acc[2][8][4];
        #pragma unroll
        for (int mi = 0; mi < 2; mi++)
            #pragma unroll
            for (int ni = 0; ni < 8; ni++)
                #pragma unroll
                for (int j = 0; j < 4; j++) acc[mi][ni][j] = 0.f;

        #pragma unroll
        for (int ksi = 0; ksi < 8; ksi++) {
            const uint32_t koff = ksi * 8 * 4;   // ks * sizeof(float)
            uint32_t a[2][4];
            #pragma unroll
            for (int mi = 0; mi < 2; mi++)
                ldsm_x4(a[mi][0], a[mi][1], a[mi][2], a[mi][3], qa[mi] + koff);
            uint32_t b[4][4];
            #pragma unroll
            for (int p = 0; p < 4; p++)
                ldsm_x4(b[p][0], b[p][1], b[p][2], b[p][3], kb[p] + koff);
            #pragma unroll
            for (int mi = 0; mi < 2; mi++)
                #pragma unroll
                for (int ni = 0; ni < 8; ni++) {
                    int p = ni >> 1, hi = (ni & 1) << 1;
                    mma_tf32u(acc[mi][ni][0], acc[mi][ni][1], acc[mi][ni][2], acc[mi][ni][3],
                              a[mi][0], a[mi][1], a[mi][2], a[mi][3],
                              b[p][hi], b[p][hi + 1]);
                }
        }

        #pragma unroll
        for (int mi = 0; mi < 2; mi++)
            #pragma unroll
            for (int ni = 0; ni < 8; ni++) {
                rp[mi][0] += __expf(scale * acc[mi][ni][0]) + __expf(scale * acc[mi][ni][1]);
                rp[mi][1] += __expf(scale * acc[mi][ni][2]) + __expf(scale * acc[mi][ni][3]);
            }
    }

    #pragma unroll
    for (int mi = 0; mi < 2; mi++)
        #pragma unroll
        for (int hh = 0; hh < 2; hh++) {
            rp[mi][hh] += __shfl_xor_sync(0xffffffffu, rp[mi][hh], 1);
            rp[mi][hh] += __shfl_xor_sync(0xffffffffu, rp[mi][hh], 2);
        }
    if (tig == 0) {
        #pragma unroll
        for (int mi = 0; mi < 2; mi++)
            #pragma unroll
            for (int hh = 0; hh < 2; hh++)
                red[wn][wm0 + mi * 16 + gid + 8 * hh] = rp[mi][hh];
    }
    __syncthreads();
    if (tid < 128) {
        long row = (long)h * S_LEN + mb * 128 + tid;
        inv[row] = 1.0f / (red[0][tid] + red[1][tid]);
    }
}

// ---------------------------------------------------------------------------
// Fused attention with LDSM fragment loads (Qs/Ks/Ps; Vs stays scalar LDS).
// ---------------------------------------------------------------------------
__global__ void __launch_bounds__(256, 2)
fused_attn_kernel(const float* __restrict__ Qp, const float* __restrict__ Kp,
                  const float* __restrict__ Vp, const float* __restrict__ invp,
                  float* __restrict__ attn, float* __restrict__ vals, float scale)
{
    extern __shared__ __align__(16) float sm[];
    const int LD = D_HEAD + 4;
    float (*Qs)[D_HEAD + 4] = (float (*)[D_HEAD + 4])sm;
    float (*Ks)[D_HEAD + 4] = (float (*)[D_HEAD + 4])(sm + 128 * LD);
    float (*Vs)[D_HEAD + 4] = (float (*)[D_HEAD + 4])(sm + 192 * LD);
    float (*Ps)[D_HEAD + 4] = (float (*)[D_HEAD + 4])(sm + 256 * LD);
    float* invs = sm + 384 * LD;

    const int mb = blockIdx.x, h = blockIdx.y;
    const float* Aq = Qp + (long)mb * 128 * D_MODEL + h * D_HEAD;
    const long attn_row0 = (long)h * S_LEN + mb * 128;

    const int tid = threadIdx.x;
    const int warp = tid >> 5;
    const int lane = tid & 31;
    const int gid = lane >> 2;
    const int tig = lane & 3;
    const int wm0 = (warp >> 1) * 32;
    const int wn0 = (warp & 1) * 32;

    const int arow = lane & 15;
    const int acol = (lane >> 4) << 2;
    const int brow = (lane & 7) + ((lane >> 4) << 3);
    const int bcol = ((lane >> 3) & 1) << 2;

    // Stage Q (tf32) and inv
    #pragma unroll
    for (int i = 0; i < 8; i++) {
        int idx = tid + i * 256;
        int r = idx >> 4;
        int c4 = (idx & 15) * 4;
        *(float4*)&Qs[r][c4] = tf32_4(*(const float4*)(Aq + (long)r * D_MODEL + c4));
    }
    if (tid < 128) invs[tid] = invp[attn_row0 + tid];

    uint32_t qa[2], pa[2];
    #pragma unroll
    for (int mi = 0; mi < 2; mi++) {
        qa[mi] = smem_u32(&Qs[wm0 + mi * 16 + arow][acol]);
        pa[mi] = smem_u32(&Ps[wm0 + mi * 16 + arow][acol]);
    }
    uint32_t kb[2];
    #pragma unroll
    for (int p = 0; p < 2; p++)
        kb[p] = smem_u32(&Ks[wn0 + p * 16 + brow][bcol]);

    float oacc[2][4][4];
    #pragma unroll
    for (int mi = 0; mi < 2; mi++)
        #pragma unroll
        for (int ni = 0; ni < 4; ni++)
            #pragma unroll
            for (int j = 0; j < 4; j++) oacc[mi][ni][j] = 0.f;

    for (int nb = 0; nb < S_LEN / D_HEAD; nb++) {
        __syncthreads();   // protect Ks/Vs/Ps from previous iteration users
        // Load K, V 64x64 tiles
        #pragma unroll
        for (int i = 0; i < 4; i++) {
            int idx = tid + i * 256;
            int r = idx >> 4;
            int c4 = (idx & 15) * 4;
            const float* gk = Kp + (long)(nb * 64 + r) * D_MODEL + h * D_HEAD + c4;
            *(float4*)&Ks[r][c4] = tf32_4(*(const float4*)gk);
            const float* gv = Vp + (long)(nb * 64 + r) * D_MODEL + h * D_HEAD + c4;
            *(float4*)&Vs[r][c4] = tf32_4(*(const float4*)gv);
        }
        __syncthreads();

        // S = Q @ K^T  (128 x 64)
        float acc[2][4][4];
        #pragma unroll
        for (int mi = 0; mi < 2; mi++)
            #pragma unroll
            for (int ni = 0; ni < 4; ni++)
                #pragma unroll
                for (int j = 0; j < 4; j++) acc[mi][ni][j] = 0.f;

        #pragma unroll
        for (int ksi = 0; ksi < 8; ksi++) {
            const uint32_t koff = ksi * 8 * 4;
            uint32_t a[2][4];
            #pragma unroll
            for (int mi = 0; mi < 2; mi++)
                ldsm_x4(a[mi][0], a[mi][1], a[mi][2], a[mi][3], qa[mi] + koff);
            uint32_t b[2][4];
            #pragma unroll
            for (int p = 0; p < 2; p++)
                ldsm_x4(b[p][0], b[p][1], b[p][2], b[p][3], kb[p] + koff);
            #pragma unroll
            for (int mi = 0; mi < 2; mi++)
                #pragma unroll
                for (int ni = 0; ni < 4; ni++) {
                    int p = ni >> 1, hi = (ni & 1) << 1;
                    mma_tf32u(acc[mi][ni][0], acc[mi][ni][1], acc[mi][ni][2], acc[mi][ni][3],
                              a[mi][0], a[mi][1], a[mi][2], a[mi][3],
                              b[p][hi], b[p][hi + 1]);
                }
        }

        // p = exp(scale*s) * inv -> Ps
        #pragma unroll
        for (int mi = 0; mi < 2; mi++) {
            int r = wm0 + mi * 16 + gid;
            float iv0 = invs[r], iv1 = invs[r + 8];
            #pragma unroll
            for (int ni = 0; ni < 4; ni++) {
                int c = wn0 + ni * 8 + tig * 2;
                *(float2*)&Ps[r][c] =
                    make_float2(__expf(scale * acc[mi][ni][0]) * iv0,
                                __expf(scale * acc[mi][ni][1]) * iv0);
                *(float2*)&Ps[r + 8][c] =
                    make_float2(__expf(scale * acc[mi][ni][2]) * iv1,
                                __expf(scale * acc[mi][ni][3]) * iv1);
            }
        }
        __syncthreads();

        // O += Ps @ Vs  (128 x 64, K=64)
        #pragma unroll
        for (int ksi = 0; ksi < 8; ksi++) {
            const int ks = ksi * 8;
            const uint32_t koff = ks * 4;
            uint32_t a[2][4];
            #pragma unroll
            for (int mi = 0; mi < 2; mi++)
                ldsm_x4(a[mi][0], a[mi][1], a[mi][2], a[mi][3], pa[mi] + koff);
            float bf[4][2];
            #pragma unroll
            for (int ni = 0; ni < 4; ni++) {
                bf[ni][0] = Vs[ks + tig][wn0 + ni * 8 + gid];
                bf[ni][1] = Vs[ks + tig + 4][wn0 + ni * 8 + gid];
            }
            #pragma unroll
            for (int mi = 0; mi < 2; mi++)
                #pragma unroll
                for (int ni = 0; ni < 4; ni++)
                    mma_tf32u(oacc[mi][ni][0], oacc[mi][ni][1], oacc[mi][ni][2], oacc[mi][ni][3],
                              a[mi][0], a[mi][1], a[mi][2], a[mi][3],
                              __float_as_uint(bf[ni][0]), __float_as_uint(bf[ni][1]));
        }

        // Write attn tile from Ps, fully coalesced float4 (128x64 = 2048 float4s)
        #pragma unroll
        for (int i = 0; i < 8; i++) {
            int idx = tid + i * 256;
            int r = idx >> 4;
            int c4 = (idx & 15) * 4;
            *(float4*)&attn[(attn_row0 + r) * S_LEN + nb * 64 + c4] =
                *(const float4*)&Ps[r][c4];
        }
    }

    // Epilogue: write O
    #pragma unroll
    for (int mi = 0; mi < 2; mi++) {
        int r0 = mb * 128 + wm0 + mi * 16 + gid;
        #pragma unroll
        for (int ni = 0; ni < 4; ni++) {
            int c = h * D_HEAD + wn0 + ni * 8 + tig * 2;
            *(float2*)&vals[(long)r0 * D_MODEL + c] =
                make_float2(oacc[mi][ni][0], oacc[mi][ni][1]);
            *(float2*)&vals[(long)(r0 + 8) * D_MODEL + c] =
                make_float2(oacc[mi][ni][2], oacc[mi][ni][3]);
        }
    }
}

extern "C" void kernel_launch(void* const* d_in, const int* in_sizes, int n_in,
                              void* d_out, int out_size)
{
    const float* q  = (const float*)d_in[0];
    const float* k  = (const float*)d_in[1];
    const float* v  = (const float*)d_in[2];
    const float* Wq = (const float*)d_in[3];
    const float* bq = (const float*)d_in[4];
    const float* Wk = (const float*)d_in[5];
    const float* bk = (const float*)d_in[6];
    const float* Wv = (const float*)d_in[7];
    const float* bv = (const float*)d_in[8];
    const float* Wo = (const float*)d_in[9];
    const float* bo = (const float*)d_in[10];

    float* out = (float*)d_out;

    float *Qp, *Kp, *Vp, *Vals, *Inv, *attn_fb;
    cudaGetSymbolAddress((void**)&Qp,   g_Qp);
    cudaGetSymbolAddress((void**)&Kp,   g_Kp);
    cudaGetSymbolAddress((void**)&Vp,   g_Vp);
    cudaGetSymbolAddress((void**)&Vals, g_vals);
    cudaGetSymbolAddress((void**)&Inv,  g_inv);
    cudaGetSymbolAddress((void**)&attn_fb, g_attn_fallback);

    const long OUT_ELEMS  = (long)S_LEN * D_MODEL;
    const long ATTN_ELEMS = (long)N_HEADS * S_LEN * S_LEN;
    float* attn = ((long)out_size >= OUT_ELEMS + ATTN_ELEMS)
                      ? (out + OUT_ELEMS)
                      : attn_fb;

    const int LD = D_HEAD + 4;
    const int ROWSUM_SMEM = 2 * 128 * LD * (int)sizeof(float);           // ~69.6 KB
    const int FUSED_SMEM  = (384 * LD + 128) * (int)sizeof(float);       // ~105 KB
    static bool attr_done = false;
    if (!attr_done) {
        cudaFuncSetAttribute(rowsum_kernel,
                             cudaFuncAttributeMaxDynamicSharedMemorySize, ROWSUM_SMEM);
        cudaFuncSetAttribute(fused_attn_kernel,
                             cudaFuncAttributeMaxDynamicSharedMemorySize, FUSED_SMEM);
        attr_done = true;
    }

    dim3 blk(256);
    const float scale = 1.0f / sqrtf((float)D_HEAD);

    // 1) QKV projections in one launch
    dim3 gQKV(D_MODEL / 128, S_LEN / 128, 3);
    qkv_proj<<<gQKV, blk>>>(q, k, v, Wq, bq, Wk, bk, Wv, bv, Qp, Kp, Vp);

    // 2) Row sums -> inv
    dim3 gRS(S_LEN / 128, N_HEADS);
    rowsum_kernel<<<gRS, blk, ROWSUM_SMEM>>>(Qp, Kp, Inv, scale);

    // 3) Fused: recompute scores, normalize, write attn once, O = P@V
    dim3 gF(S_LEN / 128, N_HEADS);
    fused_attn_kernel<<<gF, blk, FUSED_SMEM>>>(Qp, Kp, Vp, Inv, attn, Vals, scale);

    // 4) out = vals @ Wo + bo
    dim3 gProj(D_MODEL / 128, S_LEN / 128, 1);
    o_proj<<<gProj, blk>>>(Vals, Wo, out, bo);
}